// round 1
// baseline (speedup 1.0000x reference)
#include <cuda_runtime.h>
#include <cstdint>

// DifferentiableDAG: B*T independent 8-step log-space DAG executions.
// Thread = one (b,t) element. Data staged via cp.async into smem in
// transposed [element][word] layout to fix the 808B/element divergence.

constexpr int TPB = 128;   // threads (=elements) per block
constexpr int ST  = 50;    // smem row stride in floats (even for 8B cp.async, gcd(ST*... ,32) small)
constexpr int BUF = TPB * ST;  // floats per chunk buffer

extern __shared__ float smem[];  // 2 * BUF floats (double buffer)

__device__ __forceinline__ void cp_async8(uint32_t saddr, const void* gaddr) {
    asm volatile("cp.async.ca.shared.global [%0], [%1], 8;\n" :: "r"(saddr), "l"(gaddr));
}
__device__ __forceinline__ void cp_async4(uint32_t saddr, const void* gaddr) {
    asm volatile("cp.async.ca.shared.global [%0], [%1], 4;\n" :: "r"(saddr), "l"(gaddr));
}
__device__ __forceinline__ void cp_commit() { asm volatile("cp.async.commit_group;\n"); }
__device__ __forceinline__ void cp_wait_all() { asm volatile("cp.async.wait_group 0;\n" ::: "memory"); }

// clip_log(x) = 15*tanh(x/15). tanh via (1-e^{-2z})/(1+e^{-2z}), z=|x|/15.
// __expf rel err ~2^-21 -> abs err on the log value <= ~1e-5: safe for 1e-3 tol.
__device__ __forceinline__ float clip_log(float x) {
    float a = fabsf(x) * (2.0f / 15.0f);
    float t = __expf(-a);
    float u = __fdividef(1.0f - t, 1.0f + t);
    return copysignf(15.0f * u, x);
}

// Stage one chunk (2 DAG steps) for all 128 elements of this block.
// Per element: p1 18 floats (words 0..17), p2 18 (18..35), pop 10 (36..45).
__device__ __forceinline__ void issue_chunk(
    uint32_t sbuf, const float2* __restrict__ p1, const float2* __restrict__ p2,
    const float2* __restrict__ pop, int E0, int cs, int t, int elems)
{
#pragma unroll
    for (int k = 0; k < 9; k++) {               // 9 float2 per operand per elem
        int i = t + TPB * k;                    // 0..1151
        int e = i / 9, q = i - 9 * e;
        if (E0 + e < elems) {
            int g = (E0 + e) * 36 + cs * 9 + q; // float2 index into 72-float rows
            cp_async8(sbuf + 4u * (uint32_t)(e * ST + 2 * q),       p1 + g);
            cp_async8(sbuf + 4u * (uint32_t)(e * ST + 18 + 2 * q),  p2 + g);
        }
    }
#pragma unroll
    for (int k = 0; k < 5; k++) {               // 5 float2 of op-probs per elem
        int i = t + TPB * k;                    // 0..639
        int e = i / 5, q = i - 5 * e;
        if (E0 + e < elems) {
            int g = (E0 + e) * 20 + cs * 5 + q; // float2 index into 40-float rows
            cp_async8(sbuf + 4u * (uint32_t)(e * ST + 36 + 2 * q), pop + g);
        }
    }
}

__global__ void __launch_bounds__(TPB, 4)
dag_kernel(const float* __restrict__ isgn, const float* __restrict__ ilog,
           const float* __restrict__ p1f,  const float* __restrict__ p2f,
           const float* __restrict__ popf, float* __restrict__ out, int elems)
{
    const int t  = threadIdx.x;
    const int E0 = blockIdx.x * TPB;
    uint32_t s0 = (uint32_t)__cvta_generic_to_shared(smem);
    uint32_t s1 = s0 + 4u * BUF;

    const float2* p1  = (const float2*)p1f;
    const float2* p2  = (const float2*)p2f;
    const float2* pop = (const float2*)popf;

    // Prologue: chunk 0 -> buf0, initial sgn/log -> buf1 (words 0..8 / 9..17)
    issue_chunk(s0, p1, p2, pop, E0, 0, t, elems);
#pragma unroll
    for (int k = 0; k < 9; k++) {
        int i = t + TPB * k;                    // 0..1151
        int e = i / 9, j = i - 9 * e;
        if (E0 + e < elems) {
            cp_async4(s1 + 4u * (uint32_t)(e * ST + j),     isgn + (size_t)E0 * 9 + i);
            cp_async4(s1 + 4u * (uint32_t)(e * ST + 9 + j), ilog + (size_t)E0 * 9 + i);
        }
    }
    cp_commit();
    cp_wait_all();
    __syncthreads();

    float sg[9], lg[9];
    {
        const float* rowi = smem + BUF + t * ST;
#pragma unroll
        for (int j = 0; j < 9; j++) { sg[j] = rowi[j]; lg[j] = rowi[9 + j]; }
    }
    __syncthreads();   // everyone done reading buf1 before chunk1 overwrites it

    float acc = lg[0] * lg[0];   // running sum of squares of finalized logs [0..step]

#pragma unroll
    for (int cs = 0; cs < 4; cs++) {
        if (cs < 3) {
            issue_chunk((cs & 1) ? s0 : s1, p1, p2, pop, E0, cs + 1, t, elems);
            cp_commit();
        }
        const float* row = smem + ((cs & 1) ? BUF : 0) + t * ST;

#pragma unroll
        for (int sl = 0; sl < 2; sl++) {
            const int step = 2 * cs + sl;

            // ---- dot products over 9 nodes ----
            float s1v = 0.f, l1v = 0.f, s2v = 0.f, l2v = 0.f;
#pragma unroll
            for (int n = 0; n < 9; n++) {
                float a = row[sl * 9 + n];
                float b = row[18 + sl * 9 + n];
                s1v = fmaf(a, sg[n], s1v);
                l1v = fmaf(a, lg[n], l1v);
                s2v = fmaf(b, sg[n], s2v);
                l2v = fmaf(b, lg[n], l2v);
            }
            float po0 = row[36 + sl * 5 + 0];
            float po1 = row[36 + sl * 5 + 1];
            float po2 = row[36 + sl * 5 + 2];
            float po3 = row[36 + sl * 5 + 3];
            float po4 = row[36 + sl * 5 + 4];

            // ---- shared log-magnitude pieces (identical for add and sub) ----
            float dlt   = l1v - l2v;
            float m     = fmaxf(l1v, l2v);
            float l_same = clip_log(m + log1pf(__expf(-fabsf(dlt))));
            bool  bigger = (l1v >= l2v);
            float big_l  = bigger ? l1v : l2v;
            float small_l = bigger ? l2v : l1v;
            float delta  = fminf(fmaxf(small_l - big_l, -15.0f), -0.001f);
            float diffv  = log1pf(-__expf(delta));
            bool  zr     = (small_l == big_l);
            float new_l  = zr ? 0.0f : (big_l + diffv);

            bool  z1 = (s1v == 0.0f), z2 = (s2v == 0.0f);
            float prod = s1v * s2v;
            float s_sgn1 = (s1v > 0.f) ? 1.f : ((s1v < 0.f) ? -1.f : 0.f);

            // ---- ADD: sign(y) = +s2v, same_sign <=> prod > 0 ----
            float sa = 0.f, la = 0.f;
            {
                bool same_sign = (prod > 0.0f);
                float big_s = bigger ? s1v : s2v;
                float new_s = zr ? 0.0f : big_s;
                if (!z1 &&  z2) { sa = s1v; la = l1v; }
                if ( z1 && !z2) { sa = s2v; la = l2v; }
                if (!z1 && !z2) {
                    if (same_sign) { sa = s_sgn1; la = l_same; }
                    else           { sa = new_s;  la = new_l;  }
                }
                la = clip_log(la);
            }
            // ---- SUB: sy = -s2v, same_sign <=> -(prod) > 0 <=> prod < 0 ----
            float sb = 0.f, lb = 0.f;
            {
                bool same_sign = (prod < 0.0f);
                float sy = -s2v;
                float big_s = bigger ? s1v : sy;
                float new_s = zr ? 0.0f : big_s;
                if (!z1 &&  z2) { sb = s1v; lb = l1v; }
                if ( z1 && !z2) { sb = sy;  lb = l2v; }
                if (!z1 && !z2) {
                    if (same_sign) { sb = s_sgn1; lb = l_same; }
                    else           { sb = new_s;  lb = new_l;  }
                }
                lb = clip_log(lb);
            }
            // ---- MUL / DIV / ID ----
            float lm = clip_log(l1v + l2v);
            float ld = clip_log(dlt);

            // ---- probability mix (reference op order 0..4) ----
            float s_mix = po0 * sa;
            s_mix = fmaf(po1, sb,   s_mix);
            s_mix = fmaf(po2, prod, s_mix);
            s_mix = fmaf(po3, prod, s_mix);
            s_mix = fmaf(po4, s1v,  s_mix);
            float l_mix = po0 * la;
            l_mix = fmaf(po1, lb,  l_mix);
            l_mix = fmaf(po2, lm,  l_mix);
            l_mix = fmaf(po3, ld,  l_mix);
            l_mix = fmaf(po4, l1v, l_mix);
            l_mix = clip_log(l_mix);

            // ---- incremental RMS rescale over logs[0..step] + l_mix ----
            float cur = fmaf(l_mix, l_mix, acc);
            float inv = 1.0f / (float)(step + 2);           // compile-time constant
            float r   = rsqrtf(cur * inv + 1e-6f);
            float scale = fminf(15.0f * r, 1.0f);
            l_mix *= scale;

            sg[step + 1] = s_mix;
            lg[step + 1] = l_mix;
            acc = fmaf(l_mix, l_mix, acc);
        }

        if (cs < 3) { cp_wait_all(); __syncthreads(); }
    }

    if (E0 + t < elems)
        out[E0 + t] = sg[8] * expf(lg[8]);
}

extern "C" void kernel_launch(void* const* d_in, const int* in_sizes, int n_in,
                              void* d_out, int out_size)
{
    const float* isgn = (const float*)d_in[0];
    const float* ilog = (const float*)d_in[1];
    const float* p1   = (const float*)d_in[2];
    const float* p2   = (const float*)d_in[3];
    const float* pop  = (const float*)d_in[4];
    float* out = (float*)d_out;

    int elems  = in_sizes[0] / 9;                 // B*T
    int blocks = (elems + TPB - 1) / TPB;
    size_t shmem = (size_t)2 * BUF * sizeof(float);  // 51,200 B

    cudaFuncSetAttribute(dag_kernel, cudaFuncAttributeMaxDynamicSharedMemorySize, (int)shmem);
    dag_kernel<<<blocks, TPB, shmem>>>(isgn, ilog, p1, p2, pop, out, elems);
}

// round 2
// speedup vs baseline: 1.4969x; 1.4969x over previous
#include <cuda_runtime.h>
#include <cstdint>

// DifferentiableDAG: B*T independent 8-step log-space DAG executions.
// One thread per element. Per-step staging via cp.async into smem rows
// (stride 25 floats: odd => conflict-free LDS). Exploits the structural
// zeros: node n is zero until step n-1 writes it, so step s only needs
// the first s+1 operand-prob weights and a (s+1)-term dot product.

constexpr int TPB = 128;
constexpr int ST  = 25;            // floats per smem row (23 used, odd stride)
constexpr int BUF = TPB * ST;      // floats per chunk buffer

__device__ __forceinline__ void cp_async4(uint32_t saddr, const void* gaddr) {
    asm volatile("cp.async.ca.shared.global [%0], [%1], 4;\n" :: "r"(saddr), "l"(gaddr));
}
__device__ __forceinline__ void cp_commit() { asm volatile("cp.async.commit_group;\n"); }
template<int N>
__device__ __forceinline__ void cp_wait() { asm volatile("cp.async.wait_group %0;\n" :: "n"(N) : "memory"); }

// clip_log(x) = 15*tanh(x/15) via (1-e^{-2z})/(1+e^{-2z})
__device__ __forceinline__ float clip_log(float x) {
    float a = fabsf(x) * (2.0f / 15.0f);
    float t = __expf(-a);
    float u = __fdividef(1.0f - t, 1.0f + t);
    return copysignf(15.0f * u, x);
}

// Stage step S for all 128 elements: p1[0..S], p2[0..S], pop[0..4].
template<int S>
__device__ __forceinline__ void issue_chunk(
    uint32_t sbuf, const float* __restrict__ p1, const float* __restrict__ p2,
    const float* __restrict__ pop, int E0, int t)
{
    constexpr int NF = S + 1;
#pragma unroll
    for (int k = 0; k < NF; k++) {
        int i = t + TPB * k;           // 0 .. 128*NF-1
        int e = i / NF, q = i - NF * e;
        int g = (E0 + e) * 72 + S * 9 + q;
        cp_async4(sbuf + 4u * (uint32_t)(e * ST + q),     p1 + g);
        cp_async4(sbuf + 4u * (uint32_t)(e * ST + 9 + q), p2 + g);
    }
#pragma unroll
    for (int k = 0; k < 5; k++) {
        int i = t + TPB * k;
        int e = i / 5, q = i - 5 * e;
        cp_async4(sbuf + 4u * (uint32_t)(e * ST + 18 + q),
                  pop + (E0 + e) * 40 + S * 5 + q);
    }
}

template<int S>
__device__ __forceinline__ void step_compute(
    const float* __restrict__ row, float (&sg)[9], float (&lg)[9], float& acc)
{
    // ---- dot products over live nodes 0..S ----
    float s1v = 0.f, l1v = 0.f, s2v = 0.f, l2v = 0.f;
#pragma unroll
    for (int n = 0; n <= S; n++) {
        float a = row[n];
        float b = row[9 + n];
        s1v = fmaf(a, sg[n], s1v);
        l1v = fmaf(a, lg[n], l1v);
        s2v = fmaf(b, sg[n], s2v);
        l2v = fmaf(b, lg[n], l2v);
    }
    float po0 = row[18], po1 = row[19], po2 = row[20], po3 = row[21], po4 = row[22];

    // ---- shared log-magnitude pieces (identical for add and sub) ----
    float dlt    = l1v - l2v;
    float m      = fmaxf(l1v, l2v);
    float l_same = clip_log(m + __logf(1.0f + __expf(-fabsf(dlt))));
    bool  bigger = (l1v >= l2v);
    float big_l  = bigger ? l1v : l2v;
    float small_l = bigger ? l2v : l1v;
    float delta  = fminf(fmaxf(small_l - big_l, -15.0f), -0.001f);
    float diffv  = __logf(1.0f - __expf(delta));     // log1p(-exp(delta)), arg in [1e-3,1)
    bool  zr     = (small_l == big_l);
    float new_l  = zr ? 0.0f : (big_l + diffv);

    bool  z1 = (s1v == 0.0f), z2 = (s2v == 0.0f);
    float prod = s1v * s2v;
    float s_sgn1 = (s1v > 0.f) ? 1.f : ((s1v < 0.f) ? -1.f : 0.f);

    // ---- ADD ----
    float sa = 0.f, la = 0.f;
    {
        bool same_sign = (prod > 0.0f);
        float big_s = bigger ? s1v : s2v;
        float new_s = zr ? 0.0f : big_s;
        if (!z1 &&  z2) { sa = s1v; la = l1v; }
        if ( z1 && !z2) { sa = s2v; la = l2v; }
        if (!z1 && !z2) {
            if (same_sign) { sa = s_sgn1; la = l_same; }
            else           { sa = new_s;  la = new_l;  }
        }
        la = clip_log(la);
    }
    // ---- SUB (sy = -s2v) ----
    float sb = 0.f, lb = 0.f;
    {
        bool same_sign = (prod < 0.0f);
        float sy = -s2v;
        float big_s = bigger ? s1v : sy;
        float new_s = zr ? 0.0f : big_s;
        if (!z1 &&  z2) { sb = s1v; lb = l1v; }
        if ( z1 && !z2) { sb = sy;  lb = l2v; }
        if (!z1 && !z2) {
            if (same_sign) { sb = s_sgn1; lb = l_same; }
            else           { sb = new_s;  lb = new_l;  }
        }
        lb = clip_log(lb);
    }
    // ---- MUL / DIV / ID ----
    float lm = clip_log(l1v + l2v);
    float ld = clip_log(dlt);

    // ---- probability mix ----
    float s_mix = po0 * sa;
    s_mix = fmaf(po1, sb,   s_mix);
    s_mix = fmaf(po2, prod, s_mix);
    s_mix = fmaf(po3, prod, s_mix);
    s_mix = fmaf(po4, s1v,  s_mix);
    float l_mix = po0 * la;
    l_mix = fmaf(po1, lb,  l_mix);
    l_mix = fmaf(po2, lm,  l_mix);
    l_mix = fmaf(po3, ld,  l_mix);
    l_mix = fmaf(po4, l1v, l_mix);
    l_mix = clip_log(l_mix);

    // ---- incremental RMS rescale over logs[0..S] + l_mix ----
    float cur = fmaf(l_mix, l_mix, acc);
    constexpr float inv = 1.0f / (float)(S + 2);
    float r     = rsqrtf(cur * inv + 1e-6f);
    float scale = fminf(15.0f * r, 1.0f);
    l_mix *= scale;

    sg[S + 1] = s_mix;
    lg[S + 1] = l_mix;
    acc = fmaf(l_mix, l_mix, acc);
}

__global__ void __launch_bounds__(TPB, 6)
dag_kernel(const float* __restrict__ isgn, const float* __restrict__ ilog,
           const float* __restrict__ p1,   const float* __restrict__ p2,
           const float* __restrict__ pop,  float* __restrict__ out, int elems)
{
    __shared__ float smem[2 * BUF];

    const int t  = threadIdx.x;
    const int E0 = blockIdx.x * TPB;
    const int e  = E0 + t;
    uint32_t s0 = (uint32_t)__cvta_generic_to_shared(smem);
    uint32_t s1 = s0 + 4u * BUF;

    // Prefetch steps 0 and 1
    issue_chunk<0>(s0, p1, p2, pop, E0, t); cp_commit();
    issue_chunk<1>(s1, p1, p2, pop, E0, t); cp_commit();

    // Only node 0 of the initial state is nonzero (by construction).
    float sg[9], lg[9];
#pragma unroll
    for (int j = 0; j < 9; j++) { sg[j] = 0.f; lg[j] = 0.f; }
    if (e < elems) {
        sg[0] = isgn[(size_t)e * 9];
        lg[0] = ilog[(size_t)e * 9];
    }
    float acc = lg[0] * lg[0];

    const float* rowbase = smem + t * ST;

    // s=0
    cp_wait<1>(); __syncthreads();
    step_compute<0>(rowbase, sg, lg, acc);
    __syncthreads();
    issue_chunk<2>(s0, p1, p2, pop, E0, t); cp_commit();
    // s=1
    cp_wait<1>(); __syncthreads();
    step_compute<1>(rowbase + BUF, sg, lg, acc);
    __syncthreads();
    issue_chunk<3>(s1, p1, p2, pop, E0, t); cp_commit();
    // s=2
    cp_wait<1>(); __syncthreads();
    step_compute<2>(rowbase, sg, lg, acc);
    __syncthreads();
    issue_chunk<4>(s0, p1, p2, pop, E0, t); cp_commit();
    // s=3
    cp_wait<1>(); __syncthreads();
    step_compute<3>(rowbase + BUF, sg, lg, acc);
    __syncthreads();
    issue_chunk<5>(s1, p1, p2, pop, E0, t); cp_commit();
    // s=4
    cp_wait<1>(); __syncthreads();
    step_compute<4>(rowbase, sg, lg, acc);
    __syncthreads();
    issue_chunk<6>(s0, p1, p2, pop, E0, t); cp_commit();
    // s=5
    cp_wait<1>(); __syncthreads();
    step_compute<5>(rowbase + BUF, sg, lg, acc);
    __syncthreads();
    issue_chunk<7>(s1, p1, p2, pop, E0, t); cp_commit();
    // s=6
    cp_wait<1>(); __syncthreads();
    step_compute<6>(rowbase, sg, lg, acc);
    // s=7 (last chunk: drain fully)
    cp_wait<0>(); __syncthreads();
    step_compute<7>(rowbase + BUF, sg, lg, acc);

    if (e < elems)
        out[e] = sg[8] * __expf(lg[8]);
}

extern "C" void kernel_launch(void* const* d_in, const int* in_sizes, int n_in,
                              void* d_out, int out_size)
{
    const float* isgn = (const float*)d_in[0];
    const float* ilog = (const float*)d_in[1];
    const float* p1   = (const float*)d_in[2];
    const float* p2   = (const float*)d_in[3];
    const float* pop  = (const float*)d_in[4];
    float* out = (float*)d_out;

    int elems  = in_sizes[0] / 9;               // B*T
    int blocks = (elems + TPB - 1) / TPB;
    dag_kernel<<<blocks, TPB>>>(isgn, ilog, p1, p2, pop, out, elems);
}